// round 16
// baseline (speedup 1.0000x reference)
#include <cuda_runtime.h>
#include <cuda_bf16.h>
#include <math.h>
#include <stdint.h>

#define HH      512
#define BQ      128
#define MIDN    2048
#define NANS    3129
#define W2PAD   3200
#define NNODES  131072
#define NEDGES  262144

#define SEGS2   16     // row splits per (array, batch) (2 per 256-thr block)
#define ZQ      16     // split-K for fused q projection (128 gemm CTAs)
#define Z1      8      // split-K for W1
#define Z2      6      // split-K for W2 (150 CTAs)

#define QCTAS   (8 * ZQ)                  // 128
#define POOLBLK (3 * BQ * 8)              // 3072 pool blocks (2 subs each)

// ---------------- scratch (static __device__, no allocation) ----------------
__device__ int   g_segoff[3 * 129];
__device__ float g_poolpart[3 * SEGS2 * BQ * HH];
__device__ float g_qpart[ZQ * BQ * 1024];
__device__ float g_h0[BQ * 1024];
__device__ float g_h1part[Z1 * BQ * MIDN];
__device__ float g_h[BQ * MIDN];
__device__ float g_outpart[Z2 * BQ * W2PAD];

// ---------------- boundary table: one coalesced scan ------------------------
__global__ __launch_bounds__(256) void seg_bounds(const int* __restrict__ sg0,
                                                  const int* __restrict__ sg1,
                                                  const int* __restrict__ sg2) {
    int gid = blockIdx.x * 256 + threadIdx.x;
    const int stride = gridDim.x * 256;
    const int tot = NNODES + NNODES + NEDGES;
    for (int t = gid; t < tot; t += stride) {
        int arr, i, n;
        if (t < NNODES)            { arr = 0; i = t;              n = NNODES; }
        else if (t < 2 * NNODES)   { arr = 1; i = t - NNODES;     n = NNODES; }
        else                       { arr = 2; i = t - 2 * NNODES; n = NEDGES; }
        const int* seg = (arr == 0) ? sg0 : (arr == 1) ? sg1 : sg2;
        int* off = g_segoff + arr * 129;
        int v = seg[i];
        if (i == 0) {
            for (int b = 0; b <= v; ++b) off[b] = 0;
        } else {
            int pv = seg[i - 1];
            for (int b = pv + 1; b <= v; ++b) off[b] = i;
        }
        if (i == n - 1) {
            for (int b = v + 1; b <= 128; ++b) off[b] = n;
        }
    }
}

// ---------------- mma helper -------------------------------------------------
__device__ __forceinline__ void mma_bf16(float* c, const uint32_t* a,
                                         uint32_t b0, uint32_t b1) {
    asm volatile("mma.sync.aligned.m16n8k16.row.col.f32.bf16.bf16.f32 "
                 "{%0,%1,%2,%3}, {%4,%5,%6,%7}, {%8,%9}, {%0,%1,%2,%3};"
                 : "+f"(c[0]), "+f"(c[1]), "+f"(c[2]), "+f"(c[3])
                 : "r"(a[0]), "r"(a[1]), "r"(a[2]), "r"(a[3]), "r"(b0), "r"(b1));
}

// ---------------- FUSED: q-projection GEMM CTAs + pool blocks ---------------
// 1D grid of QCTAS + POOLBLK blocks. gemm blocks first -> co-scheduled with
// the first pool wave; the latency-bound gemm hides under the BW-bound pool.
__global__ __launch_bounds__(256) void pool_qgemm(const float* __restrict__ f0,
                                                  const float* __restrict__ f1,
                                                  const float* __restrict__ f2,
                                                  const float* __restrict__ question,
                                                  const float* __restrict__ Wqe,
                                                  const float* __restrict__ Wqn) {
    const int gid = blockIdx.x;
    const int tid = threadIdx.x;

    if (gid < QCTAS) {
        // ---------------- q-projection GEMM CTA (N always full) ------------
        __shared__ __align__(16) __nv_bfloat16 Ah[128][40];
        __shared__ __align__(16) __nv_bfloat16 Al[128][40];
        __shared__ __align__(16) uint32_t Bh[16][136];
        __shared__ __align__(16) uint32_t Bl[16][136];

        const int wid = tid >> 5, lane = tid & 31;
        const int wm = (wid >> 2) * 64, wn = (wid & 3) * 32;
        const int lr = lane >> 2, lc = lane & 3;

        const int nblk = gid & 7, z = gid >> 3;          // z in [0,ZQ)
        const int c0 = 2 * z, c1 = 2 * z + 2;            // 32 chunks / ZQ=16
        const int n0 = nblk * 128;
        const float* W = (n0 < 512) ? Wqe : Wqn;
        const int nb = (n0 < 512) ? n0 : n0 - 512;
        const int Nreal = 512;

        const int la_r = tid >> 3, la_c = (tid & 7) << 2;
        const int lb_r = tid >> 5, lb_c = (tid & 31) << 2;

        float4 avr[4];
        float4 b0r[2], b1r[2];
        {
            const int k0 = c0 << 5;
#pragma unroll
            for (int it = 0; it < 4; ++it)
                avr[it] = *(const float4*)(question + (size_t)(la_r + it * 32) * 1024 + k0 + la_c);
            const int k20 = k0 >> 1;
#pragma unroll
            for (int it = 0; it < 2; ++it) {
                const float* p0 = W + (size_t)((k20 + lb_r + it * 8) * 2) * Nreal + nb + lb_c;
                b0r[it] = *(const float4*)p0;
                b1r[it] = *(const float4*)(p0 + Nreal);
            }
        }

        float acc[4][4][4];
#pragma unroll
        for (int i = 0; i < 4; ++i)
#pragma unroll
            for (int j = 0; j < 4; ++j)
#pragma unroll
                for (int k = 0; k < 4; ++k) acc[i][j][k] = 0.f;

        const uint32_t* Au = (const uint32_t*)Ah;
        const uint32_t* Alu = (const uint32_t*)Al;

        for (int c = c0; c < c1; ++c) {
#pragma unroll
            for (int it = 0; it < 4; ++it) {
                float4 v = avr[it];
                int r = la_r + it * 32;
                __nv_bfloat16 h0 = __float2bfloat16_rn(v.x);
                __nv_bfloat16 h1 = __float2bfloat16_rn(v.y);
                __nv_bfloat16 h2 = __float2bfloat16_rn(v.z);
                __nv_bfloat16 h3 = __float2bfloat16_rn(v.w);
                __nv_bfloat162 hp0(h0, h1), hp1(h2, h3);
                __nv_bfloat162 lp0(__float2bfloat16_rn(v.x - __bfloat162float(h0)),
                                   __float2bfloat16_rn(v.y - __bfloat162float(h1)));
                __nv_bfloat162 lp1(__float2bfloat16_rn(v.z - __bfloat162float(h2)),
                                   __float2bfloat16_rn(v.w - __bfloat162float(h3)));
                *(uint2*)&Ah[r][la_c] = make_uint2(*(uint32_t*)&hp0, *(uint32_t*)&hp1);
                *(uint2*)&Al[r][la_c] = make_uint2(*(uint32_t*)&lp0, *(uint32_t*)&lp1);
            }
#pragma unroll
            for (int it = 0; it < 2; ++it) {
                int r = lb_r + it * 8;
                float v0[4] = {b0r[it].x, b0r[it].y, b0r[it].z, b0r[it].w};
                float v1[4] = {b1r[it].x, b1r[it].y, b1r[it].z, b1r[it].w};
                uint32_t hw[4], lw[4];
#pragma unroll
                for (int j = 0; j < 4; ++j) {
                    __nv_bfloat16 h0 = __float2bfloat16_rn(v0[j]);
                    __nv_bfloat16 h1 = __float2bfloat16_rn(v1[j]);
                    __nv_bfloat162 hp(h0, h1);
                    __nv_bfloat162 lp(__float2bfloat16_rn(v0[j] - __bfloat162float(h0)),
                                      __float2bfloat16_rn(v1[j] - __bfloat162float(h1)));
                    hw[j] = *(uint32_t*)&hp;
                    lw[j] = *(uint32_t*)&lp;
                }
                *(uint4*)&Bh[r][lb_c] = make_uint4(hw[0], hw[1], hw[2], hw[3]);
                *(uint4*)&Bl[r][lb_c] = make_uint4(lw[0], lw[1], lw[2], lw[3]);
            }
            __syncthreads();

            if (c + 1 < c1) {
                const int k0n = (c + 1) << 5;
#pragma unroll
                for (int it = 0; it < 4; ++it)
                    avr[it] = *(const float4*)(question + (size_t)(la_r + it * 32) * 1024 + k0n + la_c);
                const int k20n = k0n >> 1;
#pragma unroll
                for (int it = 0; it < 2; ++it) {
                    const float* p0 = W + (size_t)((k20n + lb_r + it * 8) * 2) * Nreal + nb + lb_c;
                    b0r[it] = *(const float4*)p0;
                    b1r[it] = *(const float4*)(p0 + Nreal);
                }
            }

#pragma unroll
            for (int ks = 0; ks < 2; ++ks) {
                const int kh = ks * 8;
                uint32_t ah[4][4], al[4][4];
#pragma unroll
                for (int mi = 0; mi < 4; ++mi) {
                    int r0 = wm + mi * 16 + lr;
                    ah[mi][0] = Au[r0 * 20 + kh + lc];
                    ah[mi][1] = Au[(r0 + 8) * 20 + kh + lc];
                    ah[mi][2] = Au[r0 * 20 + kh + 4 + lc];
                    ah[mi][3] = Au[(r0 + 8) * 20 + kh + 4 + lc];
                    al[mi][0] = Alu[r0 * 20 + kh + lc];
                    al[mi][1] = Alu[(r0 + 8) * 20 + kh + lc];
                    al[mi][2] = Alu[r0 * 20 + kh + 4 + lc];
                    al[mi][3] = Alu[(r0 + 8) * 20 + kh + 4 + lc];
                }
                uint32_t bh[4][2], bl[4][2];
#pragma unroll
                for (int ni = 0; ni < 4; ++ni) {
                    int nn = wn + ni * 8 + lr;
                    bh[ni][0] = Bh[kh + lc][nn];
                    bh[ni][1] = Bh[kh + 4 + lc][nn];
                    bl[ni][0] = Bl[kh + lc][nn];
                    bl[ni][1] = Bl[kh + 4 + lc][nn];
                }
#pragma unroll
                for (int mi = 0; mi < 4; ++mi)
#pragma unroll
                    for (int ni = 0; ni < 4; ++ni) {
                        mma_bf16(acc[mi][ni], ah[mi], bh[ni][0], bh[ni][1]);
                        mma_bf16(acc[mi][ni], ah[mi], bl[ni][0], bl[ni][1]);
                        mma_bf16(acc[mi][ni], al[mi], bh[ni][0], bh[ni][1]);
                    }
            }
            __syncthreads();
        }

#pragma unroll
        for (int mi = 0; mi < 4; ++mi)
#pragma unroll
            for (int ni = 0; ni < 4; ++ni) {
                int row = wm + mi * 16 + lr;
                int col = n0 + wn + ni * 8 + lc * 2;
                float* Cp = g_qpart + ((size_t)z * 128 + row) * 1024 + col;
                *(float2*)Cp = make_float2(acc[mi][ni][0], acc[mi][ni][1]);
                *(float2*)(Cp + (size_t)8 * 1024) = make_float2(acc[mi][ni][2], acc[mi][ni][3]);
            }
        return;
    }

    // ---------------- pool block: 2 sub-ranges of one (arr, b) --------------
    const int t = gid - QCTAS;
    const int s = t & 7, b = (t >> 3) & 127, arr = t >> 10;
    const float* feat = (arr == 0) ? f0 : (arr == 1) ? f1 : f2;
    const int sub = s * 2 + (tid >> 7);       // 16-way row split
    const int lane = tid & 127;

    int st0 = g_segoff[arr * 129 + b];
    int cnt = g_segoff[arr * 129 + b + 1] - st0;
    int r0 = st0 + (int)((long long)cnt * sub / SEGS2);
    int r1 = st0 + (int)((long long)cnt * (sub + 1) / SEGS2);

    const float4* p = (const float4*)feat + (size_t)r0 * 128 + lane;
    float4 a0 = {0,0,0,0}, a1 = a0, a2 = a0, a3 = a0, a4 = a0, a5 = a0, a6 = a0, a7 = a0;
    int r = r0;
    for (; r + 8 <= r1; r += 8) {
        float4 v0 = __ldcs(p + 0*128), v1 = __ldcs(p + 1*128);
        float4 v2 = __ldcs(p + 2*128), v3 = __ldcs(p + 3*128);
        float4 v4 = __ldcs(p + 4*128), v5 = __ldcs(p + 5*128);
        float4 v6 = __ldcs(p + 6*128), v7 = __ldcs(p + 7*128);
        a0.x+=v0.x; a0.y+=v0.y; a0.z+=v0.z; a0.w+=v0.w;
        a1.x+=v1.x; a1.y+=v1.y; a1.z+=v1.z; a1.w+=v1.w;
        a2.x+=v2.x; a2.y+=v2.y; a2.z+=v2.z; a2.w+=v2.w;
        a3.x+=v3.x; a3.y+=v3.y; a3.z+=v3.z; a3.w+=v3.w;
        a4.x+=v4.x; a4.y+=v4.y; a4.z+=v4.z; a4.w+=v4.w;
        a5.x+=v5.x; a5.y+=v5.y; a5.z+=v5.z; a5.w+=v5.w;
        a6.x+=v6.x; a6.y+=v6.y; a6.z+=v6.z; a6.w+=v6.w;
        a7.x+=v7.x; a7.y+=v7.y; a7.z+=v7.z; a7.w+=v7.w;
        p += 8 * 128;
    }
    for (; r < r1; ++r) {
        float4 v = __ldcs(p);
        a0.x+=v.x; a0.y+=v.y; a0.z+=v.z; a0.w+=v.w;
        p += 128;
    }
    float4 o;
    o.x = ((a0.x+a1.x)+(a2.x+a3.x)) + ((a4.x+a5.x)+(a6.x+a7.x));
    o.y = ((a0.y+a1.y)+(a2.y+a3.y)) + ((a4.y+a5.y)+(a6.y+a7.y));
    o.z = ((a0.z+a1.z)+(a2.z+a3.z)) + ((a4.z+a5.z)+(a6.z+a7.z));
    o.w = ((a0.w+a1.w)+(a2.w+a3.w)) + ((a4.w+a5.w)+(a6.w+a7.w));
    float4* outp = (float4*)g_poolpart + (size_t)((arr * SEGS2 + sub) * BQ + b) * 128 + lane;
    *outp = o;
}

// ---------------- standalone GEMM for W1 / W2 (unchanged) -------------------
__global__ __launch_bounds__(256) void gemm_mma_f(const float* __restrict__ A, int lda,
                                                  const float* __restrict__ B1,
                                                  const float* __restrict__ B2, int N1,
                                                  int Nreal, int NPAD,
                                                  float* __restrict__ Cpart, int K) {
    __shared__ __align__(16) __nv_bfloat16 Ah[128][40];
    __shared__ __align__(16) __nv_bfloat16 Al[128][40];
    __shared__ __align__(16) uint32_t Bh[16][136];
    __shared__ __align__(16) uint32_t Bl[16][136];

    const int tid = threadIdx.x, wid = tid >> 5, lane = tid & 31;
    const int wm = (wid >> 2) * 64, wn = (wid & 3) * 32;
    const int lr = lane >> 2, lc = lane & 3;

    const int z = blockIdx.y, Z = gridDim.y;
    const int chunks = K >> 5;
    const int c0 = chunks * z / Z, c1 = chunks * (z + 1) / Z;
    const int n0 = blockIdx.x * 128;

    const float* W; int nb;
    if (n0 < N1) { W = B1; nb = n0; } else { W = B2; nb = n0 - N1; }
    const bool full = (nb + 128 <= Nreal) && ((Nreal & 3) == 0);

    const int la_r = tid >> 3, la_c = (tid & 7) << 2;
    const int lb_r = tid >> 5, lb_c = (tid & 31) << 2;

    float4 avr[4];
    float4 b0r[2], b1r[2];
    {
        const int k0 = c0 << 5;
#pragma unroll
        for (int it = 0; it < 4; ++it)
            avr[it] = *(const float4*)(A + (size_t)(la_r + it * 32) * lda + k0 + la_c);
        const int k20 = k0 >> 1;
#pragma unroll
        for (int it = 0; it < 2; ++it) {
            const float* p0 = W + (size_t)((k20 + lb_r + it * 8) * 2) * Nreal + nb + lb_c;
            const float* p1 = p0 + Nreal;
            if (full) {
                b0r[it] = *(const float4*)p0;
                b1r[it] = *(const float4*)p1;
            } else {
                float4 x0, x1;
                x0.x = (nb + lb_c + 0 < Nreal) ? p0[0] : 0.f;
                x0.y = (nb + lb_c + 1 < Nreal) ? p0[1] : 0.f;
                x0.z = (nb + lb_c + 2 < Nreal) ? p0[2] : 0.f;
                x0.w = (nb + lb_c + 3 < Nreal) ? p0[3] : 0.f;
                x1.x = (nb + lb_c + 0 < Nreal) ? p1[0] : 0.f;
                x1.y = (nb + lb_c + 1 < Nreal) ? p1[1] : 0.f;
                x1.z = (nb + lb_c + 2 < Nreal) ? p1[2] : 0.f;
                x1.w = (nb + lb_c + 3 < Nreal) ? p1[3] : 0.f;
                b0r[it] = x0; b1r[it] = x1;
            }
        }
    }

    float acc[4][4][4];
#pragma unroll
    for (int i = 0; i < 4; ++i)
#pragma unroll
        for (int j = 0; j < 4; ++j)
#pragma unroll
            for (int k = 0; k < 4; ++k) acc[i][j][k] = 0.f;

    const uint32_t* Au = (const uint32_t*)Ah;
    const uint32_t* Alu = (const uint32_t*)Al;

    for (int c = c0; c < c1; ++c) {
#pragma unroll
        for (int it = 0; it < 4; ++it) {
            float4 v = avr[it];
            int r = la_r + it * 32;
            __nv_bfloat16 h0 = __float2bfloat16_rn(v.x);
            __nv_bfloat16 h1 = __float2bfloat16_rn(v.y);
            __nv_bfloat16 h2 = __float2bfloat16_rn(v.z);
            __nv_bfloat16 h3 = __float2bfloat16_rn(v.w);
            __nv_bfloat162 hp0(h0, h1), hp1(h2, h3);
            __nv_bfloat162 lp0(__float2bfloat16_rn(v.x - __bfloat162float(h0)),
                               __float2bfloat16_rn(v.y - __bfloat162float(h1)));
            __nv_bfloat162 lp1(__float2bfloat16_rn(v.z - __bfloat162float(h2)),
                               __float2bfloat16_rn(v.w - __bfloat162float(h3)));
            *(uint2*)&Ah[r][la_c] = make_uint2(*(uint32_t*)&hp0, *(uint32_t*)&hp1);
            *(uint2*)&Al[r][la_c] = make_uint2(*(uint32_t*)&lp0, *(uint32_t*)&lp1);
        }
#pragma unroll
        for (int it = 0; it < 2; ++it) {
            int r = lb_r + it * 8;
            float v0[4] = {b0r[it].x, b0r[it].y, b0r[it].z, b0r[it].w};
            float v1[4] = {b1r[it].x, b1r[it].y, b1r[it].z, b1r[it].w};
            uint32_t hw[4], lw[4];
#pragma unroll
            for (int j = 0; j < 4; ++j) {
                __nv_bfloat16 h0 = __float2bfloat16_rn(v0[j]);
                __nv_bfloat16 h1 = __float2bfloat16_rn(v1[j]);
                __nv_bfloat162 hp(h0, h1);
                __nv_bfloat162 lp(__float2bfloat16_rn(v0[j] - __bfloat162float(h0)),
                                  __float2bfloat16_rn(v1[j] - __bfloat162float(h1)));
                hw[j] = *(uint32_t*)&hp;
                lw[j] = *(uint32_t*)&lp;
            }
            *(uint4*)&Bh[r][lb_c] = make_uint4(hw[0], hw[1], hw[2], hw[3]);
            *(uint4*)&Bl[r][lb_c] = make_uint4(lw[0], lw[1], lw[2], lw[3]);
        }
        __syncthreads();

        if (c + 1 < c1) {
            const int k0n = (c + 1) << 5;
#pragma unroll
            for (int it = 0; it < 4; ++it)
                avr[it] = *(const float4*)(A + (size_t)(la_r + it * 32) * lda + k0n + la_c);
            const int k20n = k0n >> 1;
#pragma unroll
            for (int it = 0; it < 2; ++it) {
                const float* p0 = W + (size_t)((k20n + lb_r + it * 8) * 2) * Nreal + nb + lb_c;
                const float* p1 = p0 + Nreal;
                if (full) {
                    b0r[it] = *(const float4*)p0;
                    b1r[it] = *(const float4*)p1;
                } else {
                    float4 x0, x1;
                    x0.x = (nb + lb_c + 0 < Nreal) ? p0[0] : 0.f;
                    x0.y = (nb + lb_c + 1 < Nreal) ? p0[1] : 0.f;
                    x0.z = (nb + lb_c + 2 < Nreal) ? p0[2] : 0.f;
                    x0.w = (nb + lb_c + 3 < Nreal) ? p0[3] : 0.f;
                    x1.x = (nb + lb_c + 0 < Nreal) ? p1[0] : 0.f;
                    x1.y = (nb + lb_c + 1 < Nreal) ? p1[1] : 0.f;
                    x1.z = (nb + lb_c + 2 < Nreal) ? p1[2] : 0.f;
                    x1.w = (nb + lb_c + 3 < Nreal) ? p1[3] : 0.f;
                    b0r[it] = x0; b1r[it] = x1;
                }
            }
        }

#pragma unroll
        for (int ks = 0; ks < 2; ++ks) {
            const int kh = ks * 8;
            uint32_t ah[4][4], al[4][4];
#pragma unroll
            for (int mi = 0; mi < 4; ++mi) {
                int r0 = wm + mi * 16 + lr;
                ah[mi][0] = Au[r0 * 20 + kh + lc];
                ah[mi][1] = Au[(r0 + 8) * 20 + kh + lc];
                ah[mi][2] = Au[r0 * 20 + kh + 4 + lc];
                ah[mi][3] = Au[(r0 + 8) * 20 + kh + 4 + lc];
                al[mi][0] = Alu[r0 * 20 + kh + lc];
                al[mi][1] = Alu[(r0 + 8) * 20 + kh + lc];
                al[mi][2] = Alu[r0 * 20 + kh + 4 + lc];
                al[mi][3] = Alu[(r0 + 8) * 20 + kh + 4 + lc];
            }
            uint32_t bh[4][2], bl[4][2];
#pragma unroll
            for (int ni = 0; ni < 4; ++ni) {
                int nn = wn + ni * 8 + lr;
                bh[ni][0] = Bh[kh + lc][nn];
                bh[ni][1] = Bh[kh + 4 + lc][nn];
                bl[ni][0] = Bl[kh + lc][nn];
                bl[ni][1] = Bl[kh + 4 + lc][nn];
            }
#pragma unroll
            for (int mi = 0; mi < 4; ++mi)
#pragma unroll
                for (int ni = 0; ni < 4; ++ni) {
                    mma_bf16(acc[mi][ni], ah[mi], bh[ni][0], bh[ni][1]);
                    mma_bf16(acc[mi][ni], ah[mi], bl[ni][0], bl[ni][1]);
                    mma_bf16(acc[mi][ni], al[mi], bh[ni][0], bh[ni][1]);
                }
        }
        __syncthreads();
    }

#pragma unroll
    for (int mi = 0; mi < 4; ++mi)
#pragma unroll
        for (int ni = 0; ni < 4; ++ni) {
            int row = wm + mi * 16 + lr;
            int col = n0 + wn + ni * 8 + lc * 2;
            float* Cp = Cpart + ((size_t)z * 128 + row) * NPAD + col;
            *(float2*)Cp = make_float2(acc[mi][ni][0], acc[mi][ni][1]);
            *(float2*)(Cp + (size_t)8 * NPAD) = make_float2(acc[mi][ni][2], acc[mi][ni][3]);
        }
}

// ---------------- assemble h0 (16 pool slots, counts from table) ------------
__global__ __launch_bounds__(256) void build_h0(const float* __restrict__ bqe,
                                                const float* __restrict__ bqn) {
    __shared__ int scnt[3];
    int idx = blockIdx.x * 256 + threadIdx.x;   // 128*1024
    int b = idx >> 10, j = idx & 1023;

    if (threadIdx.x < 3) {
        int c = g_segoff[threadIdx.x * 129 + b + 1] - g_segoff[threadIdx.x * 129 + b];
        scnt[threadIdx.x] = (c < 1) ? 1 : c;
    }
    __syncthreads();

    float qs = 0.f;
#pragma unroll
    for (int z = 0; z < ZQ; ++z) qs += g_qpart[(size_t)z * (BQ * 1024) + idx];
    float r;
    if (j < 512) {
        float pe = 0.f;
#pragma unroll
        for (int s = 0; s < SEGS2; ++s)
            pe += g_poolpart[(size_t)((2 * SEGS2 + s) * BQ + b) * HH + j];
        r = 2.f * (qs + bqe[j] + pe / (float)scnt[2]);
    } else {
        int jj = j - 512;
        float p0 = 0.f, p1 = 0.f;
#pragma unroll
        for (int s = 0; s < SEGS2; ++s) {
            p0 += g_poolpart[(size_t)((0 * SEGS2 + s) * BQ + b) * HH + jj];
            p1 += g_poolpart[(size_t)((1 * SEGS2 + s) * BQ + b) * HH + jj];
        }
        r = 2.f * (qs + bqn[jj]) + p0 / (float)scnt[0] + p1 / (float)scnt[1];
    }
    g_h0[idx] = r;
}

// ---------------- reduce split-K + bias + elu -------------------------------
__global__ __launch_bounds__(256) void reduce_elu(const float* __restrict__ b1) {
    int idx = blockIdx.x * 256 + threadIdx.x;   // 128*2048
    float s = b1[idx & (MIDN - 1)];
#pragma unroll
    for (int z = 0; z < Z1; ++z) s += g_h1part[(size_t)z * (BQ * MIDN) + idx];
    g_h[idx] = (s > 0.f) ? s : expm1f(s);
}

// ---------------- reduce split-K (padded) + bias -> output ------------------
__global__ __launch_bounds__(256) void reduce_out(const float* __restrict__ b2,
                                                  float* __restrict__ out) {
    int idx = blockIdx.x * 256 + threadIdx.x;
    if (idx >= BQ * NANS) return;
    int b = idx / NANS, n = idx - b * NANS;
    float s = b2[n];
#pragma unroll
    for (int z = 0; z < Z2; ++z) s += g_outpart[((size_t)z * BQ + b) * W2PAD + n];
    out[idx] = s;
}

// ---------------- launcher ---------------------------------------------------
extern "C" void kernel_launch(void* const* d_in, const int* in_sizes, int n_in,
                              void* d_out, int out_size) {
    const float* question      = (const float*)d_in[0];
    const float* img_node_feat = (const float*)d_in[1];
    const float* kg_node_feat  = (const float*)d_in[2];
    const float* img_edge_feat = (const float*)d_in[3];
    const int*   img_node_seg  = (const int*)d_in[5];
    const int*   kg_node_seg   = (const int*)d_in[6];
    const int*   img_edge_seg  = (const int*)d_in[7];
    const float* Wqe = (const float*)d_in[9];
    const float* bqe = (const float*)d_in[10];
    const float* Wqn = (const float*)d_in[11];
    const float* bqn = (const float*)d_in[12];
    const float* W1  = (const float*)d_in[13];
    const float* b1  = (const float*)d_in[14];
    const float* W2  = (const float*)d_in[15];
    const float* b2  = (const float*)d_in[16];
    float* out = (float*)d_out;

    float *h0, *h1part, *h, *outpart;
    cudaGetSymbolAddress((void**)&h0,      g_h0);
    cudaGetSymbolAddress((void**)&h1part,  g_h1part);
    cudaGetSymbolAddress((void**)&h,       g_h);
    cudaGetSymbolAddress((void**)&outpart, g_outpart);

    // 0) boundary table
    seg_bounds<<<2048, 256>>>(img_node_seg, kg_node_seg, img_edge_seg);

    // 1) FUSED: q-projection GEMM CTAs (first, co-scheduled) + pool blocks
    pool_qgemm<<<QCTAS + POOLBLK, 256>>>(img_node_feat, kg_node_feat, img_edge_feat,
                                         question, Wqe, Wqn);

    // 2) assemble h0
    build_h0<<<(BQ * 1024) / 256, 256>>>(bqe, bqn);

    // 3) W1: 16x8 = 128 CTAs; + elu reduce
    gemm_mma_f<<<dim3(16, Z1), 256>>>(h0, 1024, W1, W1, 1 << 30, MIDN, MIDN,
                                      h1part, 1024);
    reduce_elu<<<(BQ * MIDN) / 256, 256>>>(b1);

    // 4) W2: 25x6 = 150 CTAs (odd N -> guarded B loads); + reduce
    gemm_mma_f<<<dim3(25, Z2), 256>>>(h, MIDN, W2, W2, 1 << 30, NANS, W2PAD,
                                      outpart, 2048);
    reduce_out<<<(BQ * NANS + 255) / 256, 256>>>(b2, out);
}

// round 17
// speedup vs baseline: 1.0519x; 1.0519x over previous
#include <cuda_runtime.h>
#include <cuda_bf16.h>
#include <math.h>
#include <stdint.h>

#define HH      512
#define BQ      128
#define MIDN    2048
#define NANS    3129
#define W2PAD   3200
#define NNODES  131072
#define NEDGES  262144

#define SEGS    8
#define ZQ      16     // split-K for fused q projection
#define Z1      8      // split-K for W1
#define Z2      6      // split-K for W2 (150 CTAs)

// ---------------- scratch (static __device__, no allocation) ----------------
__device__ int   g_segoff[3 * 129];
__device__ float g_poolpart[3 * SEGS * BQ * HH];
__device__ float g_qpart[ZQ * BQ * 1024];
__device__ float g_h0[BQ * 1024];
__device__ float g_h1part[Z1 * BQ * MIDN];
__device__ float g_h[BQ * MIDN];
__device__ float g_outpart[Z2 * BQ * W2PAD];

// ---------------- boundary table: one coalesced scan ------------------------
__global__ __launch_bounds__(256) void seg_bounds(const int* __restrict__ sg0,
                                                  const int* __restrict__ sg1,
                                                  const int* __restrict__ sg2) {
    int gid = blockIdx.x * 256 + threadIdx.x;
    const int stride = gridDim.x * 256;
    const int tot = NNODES + NNODES + NEDGES;
    for (int t = gid; t < tot; t += stride) {
        int arr, i, n;
        if (t < NNODES)            { arr = 0; i = t;              n = NNODES; }
        else if (t < 2 * NNODES)   { arr = 1; i = t - NNODES;     n = NNODES; }
        else                       { arr = 2; i = t - 2 * NNODES; n = NEDGES; }
        const int* seg = (arr == 0) ? sg0 : (arr == 1) ? sg1 : sg2;
        int* off = g_segoff + arr * 129;
        int v = seg[i];
        if (i == 0) {
            for (int b = 0; b <= v; ++b) off[b] = 0;
        } else {
            int pv = seg[i - 1];
            for (int b = pv + 1; b <= v; ++b) off[b] = i;
        }
        if (i == n - 1) {
            for (int b = v + 1; b <= 128; ++b) off[b] = n;
        }
    }
}

// ---------------- pool: fused segment-sum partials (3 planes, lean) ---------
__global__ __launch_bounds__(128) void seg_part(const float* __restrict__ f0,
                                                const float* __restrict__ f1,
                                                const float* __restrict__ f2) {
    int arr = blockIdx.z;
    const float* feat = (arr == 0) ? f0 : (arr == 1) ? f1 : f2;
    int b = blockIdx.y, s = blockIdx.x;

    int st0 = g_segoff[arr * 129 + b];
    int cnt = g_segoff[arr * 129 + b + 1] - st0;
    int r0 = st0 + (int)((long long)cnt * s / SEGS);
    int r1 = st0 + (int)((long long)cnt * (s + 1) / SEGS);

    const float4* p = (const float4*)feat + (size_t)r0 * 128 + threadIdx.x;
    float4 a0 = {0,0,0,0}, a1 = a0, a2 = a0, a3 = a0, a4 = a0, a5 = a0, a6 = a0, a7 = a0;
    int r = r0;
    for (; r + 8 <= r1; r += 8) {
        float4 v0 = __ldcs(p + 0*128), v1 = __ldcs(p + 1*128);
        float4 v2 = __ldcs(p + 2*128), v3 = __ldcs(p + 3*128);
        float4 v4 = __ldcs(p + 4*128), v5 = __ldcs(p + 5*128);
        float4 v6 = __ldcs(p + 6*128), v7 = __ldcs(p + 7*128);
        a0.x+=v0.x; a0.y+=v0.y; a0.z+=v0.z; a0.w+=v0.w;
        a1.x+=v1.x; a1.y+=v1.y; a1.z+=v1.z; a1.w+=v1.w;
        a2.x+=v2.x; a2.y+=v2.y; a2.z+=v2.z; a2.w+=v2.w;
        a3.x+=v3.x; a3.y+=v3.y; a3.z+=v3.z; a3.w+=v3.w;
        a4.x+=v4.x; a4.y+=v4.y; a4.z+=v4.z; a4.w+=v4.w;
        a5.x+=v5.x; a5.y+=v5.y; a5.z+=v5.z; a5.w+=v5.w;
        a6.x+=v6.x; a6.y+=v6.y; a6.z+=v6.z; a6.w+=v6.w;
        a7.x+=v7.x; a7.y+=v7.y; a7.z+=v7.z; a7.w+=v7.w;
        p += 8 * 128;
    }
    for (; r < r1; ++r) {
        float4 v = __ldcs(p);
        a0.x+=v.x; a0.y+=v.y; a0.z+=v.z; a0.w+=v.w;
        p += 128;
    }
    float4 t;
    t.x = ((a0.x+a1.x)+(a2.x+a3.x)) + ((a4.x+a5.x)+(a6.x+a7.x));
    t.y = ((a0.y+a1.y)+(a2.y+a3.y)) + ((a4.y+a5.y)+(a6.y+a7.y));
    t.z = ((a0.z+a1.z)+(a2.z+a3.z)) + ((a4.z+a5.z)+(a6.z+a7.z));
    t.w = ((a0.w+a1.w)+(a2.w+a3.w)) + ((a4.w+a5.w)+(a6.w+a7.w));
    float4* outp = (float4*)g_poolpart + (size_t)((arr * SEGS + s) * BQ + b) * 128 + threadIdx.x;
    *outp = t;
}

// ---------------- bf16 mma.sync GEMM, fused conversion, reg-prefetch --------
__device__ __forceinline__ void mma_bf16(float* c, const uint32_t* a,
                                         uint32_t b0, uint32_t b1) {
    asm volatile("mma.sync.aligned.m16n8k16.row.col.f32.bf16.bf16.f32 "
                 "{%0,%1,%2,%3}, {%4,%5,%6,%7}, {%8,%9}, {%0,%1,%2,%3};"
                 : "+f"(c[0]), "+f"(c[1]), "+f"(c[2]), "+f"(c[3])
                 : "r"(a[0]), "r"(a[1]), "r"(a[2]), "r"(a[3]), "r"(b0), "r"(b1));
}

__global__ __launch_bounds__(256) void gemm_mma_f(const float* __restrict__ A, int lda,
                                                  const float* __restrict__ B1,
                                                  const float* __restrict__ B2, int N1,
                                                  int Nreal, int NPAD,
                                                  float* __restrict__ Cpart, int K) {
    __shared__ __align__(16) __nv_bfloat16 Ah[128][40];
    __shared__ __align__(16) __nv_bfloat16 Al[128][40];
    __shared__ __align__(16) uint32_t Bh[16][136];
    __shared__ __align__(16) uint32_t Bl[16][136];

    const int tid = threadIdx.x, wid = tid >> 5, lane = tid & 31;
    const int wm = (wid >> 2) * 64, wn = (wid & 3) * 32;
    const int lr = lane >> 2, lc = lane & 3;

    const int z = blockIdx.y, Z = gridDim.y;
    const int chunks = K >> 5;
    const int c0 = chunks * z / Z, c1 = chunks * (z + 1) / Z;
    const int n0 = blockIdx.x * 128;

    const float* W; int nb;
    if (n0 < N1) { W = B1; nb = n0; } else { W = B2; nb = n0 - N1; }
    const bool full = (nb + 128 <= Nreal) && ((Nreal & 3) == 0);

    const int la_r = tid >> 3, la_c = (tid & 7) << 2;
    const int lb_r = tid >> 5, lb_c = (tid & 31) << 2;

    float4 avr[4];
    float4 b0r[2], b1r[2];
    {
        const int k0 = c0 << 5;
#pragma unroll
        for (int it = 0; it < 4; ++it)
            avr[it] = *(const float4*)(A + (size_t)(la_r + it * 32) * lda + k0 + la_c);
        const int k20 = k0 >> 1;
#pragma unroll
        for (int it = 0; it < 2; ++it) {
            const float* p0 = W + (size_t)((k20 + lb_r + it * 8) * 2) * Nreal + nb + lb_c;
            const float* p1 = p0 + Nreal;
            if (full) {
                b0r[it] = *(const float4*)p0;
                b1r[it] = *(const float4*)p1;
            } else {
                float4 x0, x1;
                x0.x = (nb + lb_c + 0 < Nreal) ? p0[0] : 0.f;
                x0.y = (nb + lb_c + 1 < Nreal) ? p0[1] : 0.f;
                x0.z = (nb + lb_c + 2 < Nreal) ? p0[2] : 0.f;
                x0.w = (nb + lb_c + 3 < Nreal) ? p0[3] : 0.f;
                x1.x = (nb + lb_c + 0 < Nreal) ? p1[0] : 0.f;
                x1.y = (nb + lb_c + 1 < Nreal) ? p1[1] : 0.f;
                x1.z = (nb + lb_c + 2 < Nreal) ? p1[2] : 0.f;
                x1.w = (nb + lb_c + 3 < Nreal) ? p1[3] : 0.f;
                b0r[it] = x0; b1r[it] = x1;
            }
        }
    }

    float acc[4][4][4];
#pragma unroll
    for (int i = 0; i < 4; ++i)
#pragma unroll
        for (int j = 0; j < 4; ++j)
#pragma unroll
            for (int k = 0; k < 4; ++k) acc[i][j][k] = 0.f;

    const uint32_t* Au = (const uint32_t*)Ah;
    const uint32_t* Alu = (const uint32_t*)Al;

    for (int c = c0; c < c1; ++c) {
#pragma unroll
        for (int it = 0; it < 4; ++it) {
            float4 v = avr[it];
            int r = la_r + it * 32;
            __nv_bfloat16 h0 = __float2bfloat16_rn(v.x);
            __nv_bfloat16 h1 = __float2bfloat16_rn(v.y);
            __nv_bfloat16 h2 = __float2bfloat16_rn(v.z);
            __nv_bfloat16 h3 = __float2bfloat16_rn(v.w);
            __nv_bfloat162 hp0(h0, h1), hp1(h2, h3);
            __nv_bfloat162 lp0(__float2bfloat16_rn(v.x - __bfloat162float(h0)),
                               __float2bfloat16_rn(v.y - __bfloat162float(h1)));
            __nv_bfloat162 lp1(__float2bfloat16_rn(v.z - __bfloat162float(h2)),
                               __float2bfloat16_rn(v.w - __bfloat162float(h3)));
            *(uint2*)&Ah[r][la_c] = make_uint2(*(uint32_t*)&hp0, *(uint32_t*)&hp1);
            *(uint2*)&Al[r][la_c] = make_uint2(*(uint32_t*)&lp0, *(uint32_t*)&lp1);
        }
#pragma unroll
        for (int it = 0; it < 2; ++it) {
            int r = lb_r + it * 8;
            float v0[4] = {b0r[it].x, b0r[it].y, b0r[it].z, b0r[it].w};
            float v1[4] = {b1r[it].x, b1r[it].y, b1r[it].z, b1r[it].w};
            uint32_t hw[4], lw[4];
#pragma unroll
            for (int j = 0; j < 4; ++j) {
                __nv_bfloat16 h0 = __float2bfloat16_rn(v0[j]);
                __nv_bfloat16 h1 = __float2bfloat16_rn(v1[j]);
                __nv_bfloat162 hp(h0, h1);
                __nv_bfloat162 lp(__float2bfloat16_rn(v0[j] - __bfloat162float(h0)),
                                  __float2bfloat16_rn(v1[j] - __bfloat162float(h1)));
                hw[j] = *(uint32_t*)&hp;
                lw[j] = *(uint32_t*)&lp;
            }
            *(uint4*)&Bh[r][lb_c] = make_uint4(hw[0], hw[1], hw[2], hw[3]);
            *(uint4*)&Bl[r][lb_c] = make_uint4(lw[0], lw[1], lw[2], lw[3]);
        }
        __syncthreads();

        if (c + 1 < c1) {
            const int k0n = (c + 1) << 5;
#pragma unroll
            for (int it = 0; it < 4; ++it)
                avr[it] = *(const float4*)(A + (size_t)(la_r + it * 32) * lda + k0n + la_c);
            const int k20n = k0n >> 1;
#pragma unroll
            for (int it = 0; it < 2; ++it) {
                const float* p0 = W + (size_t)((k20n + lb_r + it * 8) * 2) * Nreal + nb + lb_c;
                const float* p1 = p0 + Nreal;
                if (full) {
                    b0r[it] = *(const float4*)p0;
                    b1r[it] = *(const float4*)p1;
                } else {
                    float4 x0, x1;
                    x0.x = (nb + lb_c + 0 < Nreal) ? p0[0] : 0.f;
                    x0.y = (nb + lb_c + 1 < Nreal) ? p0[1] : 0.f;
                    x0.z = (nb + lb_c + 2 < Nreal) ? p0[2] : 0.f;
                    x0.w = (nb + lb_c + 3 < Nreal) ? p0[3] : 0.f;
                    x1.x = (nb + lb_c + 0 < Nreal) ? p1[0] : 0.f;
                    x1.y = (nb + lb_c + 1 < Nreal) ? p1[1] : 0.f;
                    x1.z = (nb + lb_c + 2 < Nreal) ? p1[2] : 0.f;
                    x1.w = (nb + lb_c + 3 < Nreal) ? p1[3] : 0.f;
                    b0r[it] = x0; b1r[it] = x1;
                }
            }
        }

#pragma unroll
        for (int ks = 0; ks < 2; ++ks) {
            const int kh = ks * 8;
            uint32_t ah[4][4], al[4][4];
#pragma unroll
            for (int mi = 0; mi < 4; ++mi) {
                int r0 = wm + mi * 16 + lr;
                ah[mi][0] = Au[r0 * 20 + kh + lc];
                ah[mi][1] = Au[(r0 + 8) * 20 + kh + lc];
                ah[mi][2] = Au[r0 * 20 + kh + 4 + lc];
                ah[mi][3] = Au[(r0 + 8) * 20 + kh + 4 + lc];
                al[mi][0] = Alu[r0 * 20 + kh + lc];
                al[mi][1] = Alu[(r0 + 8) * 20 + kh + lc];
                al[mi][2] = Alu[r0 * 20 + kh + 4 + lc];
                al[mi][3] = Alu[(r0 + 8) * 20 + kh + 4 + lc];
            }
            uint32_t bh[4][2], bl[4][2];
#pragma unroll
            for (int ni = 0; ni < 4; ++ni) {
                int nn = wn + ni * 8 + lr;
                bh[ni][0] = Bh[kh + lc][nn];
                bh[ni][1] = Bh[kh + 4 + lc][nn];
                bl[ni][0] = Bl[kh + lc][nn];
                bl[ni][1] = Bl[kh + 4 + lc][nn];
            }
#pragma unroll
            for (int mi = 0; mi < 4; ++mi)
#pragma unroll
                for (int ni = 0; ni < 4; ++ni) {
                    mma_bf16(acc[mi][ni], ah[mi], bh[ni][0], bh[ni][1]);
                    mma_bf16(acc[mi][ni], ah[mi], bl[ni][0], bl[ni][1]);
                    mma_bf16(acc[mi][ni], al[mi], bh[ni][0], bh[ni][1]);
                }
        }
        __syncthreads();
    }

#pragma unroll
    for (int mi = 0; mi < 4; ++mi)
#pragma unroll
        for (int ni = 0; ni < 4; ++ni) {
            int row = wm + mi * 16 + lr;
            int col = n0 + wn + ni * 8 + lc * 2;
            float* Cp = Cpart + ((size_t)z * 128 + row) * NPAD + col;
            *(float2*)Cp = make_float2(acc[mi][ni][0], acc[mi][ni][1]);
            *(float2*)(Cp + (size_t)8 * NPAD) = make_float2(acc[mi][ni][2], acc[mi][ni][3]);
        }
}

// ---------------- assemble h0 (float4; 1 block per batch row) ---------------
__global__ __launch_bounds__(256) void build_h0(const float* __restrict__ bqe,
                                                const float* __restrict__ bqn) {
    __shared__ int scnt[3];
    const int b = blockIdx.x;                 // 128 blocks
    const int j4 = threadIdx.x;               // 256 threads x 4 cols = 1024
    const int j = j4 << 2;

    if (threadIdx.x < 3) {
        int c = g_segoff[threadIdx.x * 129 + b + 1] - g_segoff[threadIdx.x * 129 + b];
        scnt[threadIdx.x] = (c < 1) ? 1 : c;
    }
    __syncthreads();

    const size_t base = (size_t)b * 1024 + j;
    float4 qs = {0.f, 0.f, 0.f, 0.f};
#pragma unroll
    for (int z = 0; z < ZQ; ++z) {
        float4 v = *(const float4*)(g_qpart + (size_t)z * (BQ * 1024) + base);
        qs.x += v.x; qs.y += v.y; qs.z += v.z; qs.w += v.w;
    }
    float4 r;
    if (j < 512) {
        float4 pe = {0.f, 0.f, 0.f, 0.f};
#pragma unroll
        for (int s = 0; s < SEGS; ++s) {
            float4 v = *(const float4*)(g_poolpart + (size_t)((2 * SEGS + s) * BQ + b) * HH + j);
            pe.x += v.x; pe.y += v.y; pe.z += v.z; pe.w += v.w;
        }
        float4 be = *(const float4*)(bqe + j);
        float inv = 1.f / (float)scnt[2];
        r.x = 2.f * (qs.x + be.x + pe.x * inv);
        r.y = 2.f * (qs.y + be.y + pe.y * inv);
        r.z = 2.f * (qs.z + be.z + pe.z * inv);
        r.w = 2.f * (qs.w + be.w + pe.w * inv);
    } else {
        int jj = j - 512;
        float4 p0 = {0.f, 0.f, 0.f, 0.f}, p1 = p0;
#pragma unroll
        for (int s = 0; s < SEGS; ++s) {
            float4 v0 = *(const float4*)(g_poolpart + (size_t)((0 * SEGS + s) * BQ + b) * HH + jj);
            float4 v1 = *(const float4*)(g_poolpart + (size_t)((1 * SEGS + s) * BQ + b) * HH + jj);
            p0.x += v0.x; p0.y += v0.y; p0.z += v0.z; p0.w += v0.w;
            p1.x += v1.x; p1.y += v1.y; p1.z += v1.z; p1.w += v1.w;
        }
        float4 bn = *(const float4*)(bqn + jj);
        float i0 = 1.f / (float)scnt[0], i1 = 1.f / (float)scnt[1];
        r.x = 2.f * (qs.x + bn.x) + p0.x * i0 + p1.x * i1;
        r.y = 2.f * (qs.y + bn.y) + p0.y * i0 + p1.y * i1;
        r.z = 2.f * (qs.z + bn.z) + p0.z * i0 + p1.z * i1;
        r.w = 2.f * (qs.w + bn.w) + p0.w * i0 + p1.w * i1;
    }
    *(float4*)(g_h0 + base) = r;
}

// ---------------- reduce split-K + bias + elu (float4) ----------------------
__global__ __launch_bounds__(256) void reduce_elu(const float* __restrict__ b1) {
    int i4 = blockIdx.x * 256 + threadIdx.x;  // over 128*2048/4
    size_t base = (size_t)i4 << 2;
    float4 s = *(const float4*)(b1 + (base & (MIDN - 1)));
#pragma unroll
    for (int z = 0; z < Z1; ++z) {
        float4 v = *(const float4*)(g_h1part + (size_t)z * (BQ * MIDN) + base);
        s.x += v.x; s.y += v.y; s.z += v.z; s.w += v.w;
    }
    float4 o;
    o.x = (s.x > 0.f) ? s.x : expm1f(s.x);
    o.y = (s.y > 0.f) ? s.y : expm1f(s.y);
    o.z = (s.z > 0.f) ? s.z : expm1f(s.z);
    o.w = (s.w > 0.f) ? s.w : expm1f(s.w);
    *(float4*)(g_h + base) = o;
}

// ---------------- reduce split-K (padded) + bias -> output ------------------
// float4 loads from the aligned padded partials; scalar stores (NANS odd).
__global__ __launch_bounds__(256) void reduce_out(const float* __restrict__ b2,
                                                  float* __restrict__ out) {
    int t = blockIdx.x * 256 + threadIdx.x;   // over BQ * ceil(NANS/4)
    const int nq = (NANS + 3) >> 2;           // 783
    int b = t / nq, n4 = t - b * nq;
    if (b >= BQ) return;
    int n = n4 << 2;
    float4 s = {0.f, 0.f, 0.f, 0.f};
#pragma unroll
    for (int z = 0; z < Z2; ++z) {
        float4 v = *(const float4*)(g_outpart + ((size_t)z * BQ + b) * W2PAD + n);
        s.x += v.x; s.y += v.y; s.z += v.z; s.w += v.w;
    }
    float* op = out + (size_t)b * NANS + n;
    if (n + 4 <= NANS) {
        op[0] = s.x + b2[n];
        op[1] = s.y + b2[n + 1];
        op[2] = s.z + b2[n + 2];
        op[3] = s.w + b2[n + 3];
    } else {
        float sv[4] = {s.x, s.y, s.z, s.w};
        for (int j = 0; n + j < NANS; ++j) op[j] = sv[j] + b2[n + j];
    }
}

// ---------------- launcher ---------------------------------------------------
extern "C" void kernel_launch(void* const* d_in, const int* in_sizes, int n_in,
                              void* d_out, int out_size) {
    const float* question      = (const float*)d_in[0];
    const float* img_node_feat = (const float*)d_in[1];
    const float* kg_node_feat  = (const float*)d_in[2];
    const float* img_edge_feat = (const float*)d_in[3];
    const int*   img_node_seg  = (const int*)d_in[5];
    const int*   kg_node_seg   = (const int*)d_in[6];
    const int*   img_edge_seg  = (const int*)d_in[7];
    const float* Wqe = (const float*)d_in[9];
    const float* bqe = (const float*)d_in[10];
    const float* Wqn = (const float*)d_in[11];
    const float* bqn = (const float*)d_in[12];
    const float* W1  = (const float*)d_in[13];
    const float* b1  = (const float*)d_in[14];
    const float* W2  = (const float*)d_in[15];
    const float* b2  = (const float*)d_in[16];
    float* out = (float*)d_out;

    float *qpart, *h0, *h1part, *h, *outpart;
    cudaGetSymbolAddress((void**)&qpart,   g_qpart);
    cudaGetSymbolAddress((void**)&h0,      g_h0);
    cudaGetSymbolAddress((void**)&h1part,  g_h1part);
    cudaGetSymbolAddress((void**)&h,       g_h);
    cudaGetSymbolAddress((void**)&outpart, g_outpart);

    // 0) boundary table
    seg_bounds<<<2048, 256>>>(img_node_seg, kg_node_seg, img_edge_seg);

    // 1) pools (lean 128-thread blocks, at the HBM wall)
    seg_part<<<dim3(SEGS, BQ, 3), 128>>>(img_node_feat, kg_node_feat, img_edge_feat);

    // 2) fused q projection (pipelined): 8x16 = 128 CTAs
    gemm_mma_f<<<dim3(8, ZQ), 256>>>(question, 1024, Wqe, Wqn, 512, 512, 1024,
                                     qpart, 1024);

    // 3) assemble h0 (vectorized, 1 block per batch)
    build_h0<<<BQ, 256>>>(bqe, bqn);

    // 4) W1 (pipelined): 16x8 = 128 CTAs; + elu reduce (vectorized)
    gemm_mma_f<<<dim3(16, Z1), 256>>>(h0, 1024, W1, W1, 1 << 30, MIDN, MIDN,
                                      h1part, 1024);
    reduce_elu<<<(BQ * MIDN / 4) / 256, 256>>>(b1);

    // 5) W2 (pipelined): 25x6 = 150 CTAs; + reduce (vectorized loads)
    gemm_mma_f<<<dim3(25, Z2), 256>>>(h, MIDN, W2, W2, 1 << 30, NANS, W2PAD,
                                      outpart, 2048);
    reduce_out<<<(BQ * ((NANS + 3) / 4) + 255) / 256, 256>>>(b2, out);
}